// round 15
// baseline (speedup 1.0000x reference)
#include <cuda_runtime.h>
#include <cfloat>
#include <cstdint>

#define BHW 8192
#define CDIM 256
#define NE 16384
#define NSPL 128           // n-splits of 128 codes each
#define TILES 8192         // 64 row-blocks x 128 n-splits
#define GRIDX 296          // 148 SMs x 2 CTAs

typedef unsigned long long u64;

// ---------------- scratch (no allocations allowed) ----------------
__device__ float g_zt2[CDIM * 2 * BHW]; // K-major DUPLICATED z: [c][2r]=[2r+1], 16 MB
__device__ float g_Et[CDIM * NE];       // K-major codebook: [c][n], 16 MB
__device__ float g_A[BHW];              // reference-faithful ||z_row||^2 (strict sequential)
__device__ float g_bestval[NSPL * BHW];
__device__ int   g_bestidx[NSPL * BHW];
__device__ int   g_idx[BHW];
__device__ float g_losspart[2048];

// ---------------- packed f32x2 helpers (each lane = independent rn fma) -----
__device__ __forceinline__ u64 fma2(u64 a, u64 b, u64 c) {
    u64 d; asm("fma.rn.f32x2 %0, %1, %2, %3;" : "=l"(d) : "l"(a), "l"(b), "l"(c));
    return d;
}
__device__ __forceinline__ void unpack2(u64 v, float& lo, float& hi) {
    asm("mov.b64 {%0, %1}, %2;" : "=f"(lo), "=f"(hi) : "l"(v));
}
__device__ __forceinline__ void cp16(uint32_t dst, const float* src) {
    asm volatile("cp.async.cg.shared.global [%0], [%1], 16;" :: "r"(dst), "l"(src));
}
__device__ __forceinline__ void cp_commit() {
    asm volatile("cp.async.commit_group;" ::: "memory");
}
__device__ __forceinline__ void cp_wait1() {
    asm volatile("cp.async.wait_group 1;" ::: "memory");
}
__device__ __forceinline__ void cp_wait0() {
    asm volatile("cp.async.wait_group 0;" ::: "memory");
}

// Stage layout (floats): As2[32][264] (128 rows duplicated + pad), then Bs[32][132].
#define AS2_ROW 264
#define BS_ROW 132
#define AS2_FLOATS (32 * AS2_ROW)          // 8448
#define STAGE_FLOATS (AS2_FLOATS + 32 * BS_ROW)  // 12672

// ---------------- 1) z (B,C,HW) -> zt2[c][2*(b*1024+hw)] duplicated ----------
__global__ void k_zcopy(const float* __restrict__ z) {
    int i = blockIdx.x * 256 + threadIdx.x;    // 2,097,152 elements
    int hw = i & 1023;
    int c  = (i >> 10) & 255;
    int b  = i >> 18;
    float v = z[i];
    ((float2*)g_zt2)[c * BHW + b * 1024 + hw] = make_float2(v, v);
}

// ---------------- 2) E [n][c] -> Et [c][n] tiled transpose -------------------
__global__ void k_etrans(const float* __restrict__ E) {
    __shared__ float t[32][33];
    int n0 = blockIdx.x * 32, c0 = blockIdx.y * 32;
    int tx = threadIdx.x, ty = threadIdx.y;
    t[ty][tx] = E[(n0 + ty) * CDIM + c0 + tx];
    __syncthreads();
    g_Et[(c0 + ty) * NE + n0 + tx] = t[tx][ty];
}

// ---------------- 3) A = sum(z_c^2), STRICT sequential c=0..255 --------------
// (square rounded separately, then sequential adds — replicates XLA:CPU)
__global__ void k_rownorm(void) {
    int row = blockIdx.x * blockDim.x + threadIdx.x;
    if (row >= BHW) return;
    float acc = 0.0f;
    #pragma unroll 8
    for (int c = 0; c < CDIM; c++) {
        float v = g_zt2[c * 2 * BHW + 2 * row];
        acc = __fadd_rn(acc, __fmul_rn(v, v));
    }
    g_A[row] = acc;
}

// ---------------- 4) persistent GEMM (f32x2, zero-pack) + argmin -------------
// acc lanes = (n_even, n_odd) of one row; a-dup pairs come straight from the
// duplicated As2 LDS.128, b pairs from Bs LDS.128 -> no pack MOVs in the loop.
// Each lane is an independent k-ascending rn fma chain -> bit-exact.
// d = fl(A - 2g); ties -> lowest n (jp asc, lo->hi, ns ascending in finalize).
__global__ __launch_bounds__(256, 2) void k_gemm_argmin(void) {
    extern __shared__ float smem[];
    uint32_t sb;
    asm("{ .reg .u64 t; cvta.to.shared.u64 t, %1; cvt.u32.u64 %0, t; }"
        : "=r"(sb) : "l"(smem));
    const int tid = threadIdx.x;
    const int tx = tid & 15;          // n group (8 cols)
    const int ty = tid >> 4;          // row group (8 rows)

    for (int t = blockIdx.x; t < TILES; t += GRIDX) {
        const int rblk = t >> 7;
        const int ns   = t & 127;
        const int row0 = rblk * 128;
        const int n0   = ns * 128;

        float a_norm[8];
        #pragma unroll
        for (int i = 0; i < 8; i++) a_norm[i] = g_A[row0 + ty * 8 + i];

        // ---- prologue: issue stage 0 (k0=0) into buf 0 ----
        #pragma unroll
        for (int l = 0; l < 8; l++) {          // As2: 2048 float4
            int fid = tid + l * 256;
            int kk = fid >> 6;
            int q = (fid & 63) * 4;
            cp16(sb + (uint32_t)(kk * AS2_ROW + q) * 4,
                 g_zt2 + (size_t)kk * (2 * BHW) + 2 * row0 + q);
        }
        #pragma unroll
        for (int l = 0; l < 4; l++) {          // Bs: 1024 float4
            int fid = tid + l * 256;
            int kk = fid >> 5;
            int q4 = (fid & 31) * 4;
            cp16(sb + (uint32_t)(AS2_FLOATS + kk * BS_ROW + q4) * 4,
                 g_Et + (size_t)kk * NE + n0 + q4);
        }
        cp_commit();

        u64 acc[8][4];                 // [row][n-pair]; (0.f,0.f) == 0ull
        #pragma unroll
        for (int i = 0; i < 8; i++)
            #pragma unroll
            for (int jp = 0; jp < 4; jp++) acc[i][jp] = 0ull;

        for (int s = 0; s < 8; s++) {
            if (s + 1 < 8) {           // issue stage s+1 into alternate buffer
                const int k01 = (s + 1) * 32;
                const uint32_t bofs = (uint32_t)(((s + 1) & 1) * STAGE_FLOATS) * 4;
                #pragma unroll
                for (int l = 0; l < 8; l++) {
                    int fid = tid + l * 256;
                    int kk = fid >> 6;
                    int q = (fid & 63) * 4;
                    cp16(sb + bofs + (uint32_t)(kk * AS2_ROW + q) * 4,
                         g_zt2 + (size_t)(k01 + kk) * (2 * BHW) + 2 * row0 + q);
                }
                #pragma unroll
                for (int l = 0; l < 4; l++) {
                    int fid = tid + l * 256;
                    int kk = fid >> 5;
                    int q4 = (fid & 31) * 4;
                    cp16(sb + bofs + (uint32_t)(AS2_FLOATS + kk * BS_ROW + q4) * 4,
                         g_Et + (size_t)(k01 + kk) * NE + n0 + q4);
                }
                cp_commit();
                cp_wait1();            // stage s complete
            } else {
                cp_wait0();
            }
            __syncthreads();

            const float* as = smem + (s & 1) * STAGE_FLOATS;
            const float* bs = as + AS2_FLOATS;

            #pragma unroll
            for (int k = 0; k < 32; k++) {
                // a: duplicated rows -> u64 lanes are (a_r, a_r)
                float4 a0 = *(const float4*)(as + k * AS2_ROW + ty * 16);
                float4 a1 = *(const float4*)(as + k * AS2_ROW + ty * 16 + 4);
                float4 a2 = *(const float4*)(as + k * AS2_ROW + ty * 16 + 8);
                float4 a3 = *(const float4*)(as + k * AS2_ROW + ty * 16 + 12);
                // b: u64 lanes are (b_{2j}, b_{2j+1})
                float4 b0 = *(const float4*)(bs + k * BS_ROW + tx * 8);
                float4 b1 = *(const float4*)(bs + k * BS_ROW + tx * 8 + 4);
                u64 ad[8];
                ad[0] = ((const u64*)&a0)[0]; ad[1] = ((const u64*)&a0)[1];
                ad[2] = ((const u64*)&a1)[0]; ad[3] = ((const u64*)&a1)[1];
                ad[4] = ((const u64*)&a2)[0]; ad[5] = ((const u64*)&a2)[1];
                ad[6] = ((const u64*)&a3)[0]; ad[7] = ((const u64*)&a3)[1];
                u64 bp[4];
                bp[0] = ((const u64*)&b0)[0]; bp[1] = ((const u64*)&b0)[1];
                bp[2] = ((const u64*)&b1)[0]; bp[3] = ((const u64*)&b1)[1];
                #pragma unroll
                for (int i = 0; i < 8; i++)
                    #pragma unroll
                    for (int jp = 0; jp < 4; jp++)
                        acc[i][jp] = fma2(ad[i], bp[jp], acc[i][jp]);
            }
            __syncthreads();           // compute done before buffer reuse
        }

        // ---- epilogue: d = fl(A - 2g); n ascending (jp asc, lo->hi) ----
        float bestv[8];
        int   besti[8];
        #pragma unroll
        for (int i = 0; i < 8; i++) { bestv[i] = FLT_MAX; besti[i] = 0x7FFFFFFF; }
        #pragma unroll
        for (int i = 0; i < 8; i++) {
            #pragma unroll
            for (int jp = 0; jp < 4; jp++) {
                float glo, ghi;
                unpack2(acc[i][jp], glo, ghi);
                int n = n0 + tx * 8 + jp * 2;
                float dlo = __fmaf_rn(-2.0f, glo, a_norm[i]);
                if (dlo < bestv[i]) { bestv[i] = dlo; besti[i] = n; }
                float dhi = __fmaf_rn(-2.0f, ghi, a_norm[i]);
                if (dhi < bestv[i]) { bestv[i] = dhi; besti[i] = n + 1; }
            }
        }

        // ---- cross-thread (tx) reduction; reuse buf0 as scratch ----
        float* redv = smem;                 // 2048 floats
        int*   redi = (int*)(smem + 2048);  // 2048 ints
        #pragma unroll
        for (int i = 0; i < 8; i++) {
            int rl = ty * 8 + i;
            redv[rl * 16 + tx] = bestv[i];
            redi[rl * 16 + tx] = besti[i];
        }
        __syncthreads();
        if (tid < 128) {
            float bv = redv[tid * 16];
            int bi = redi[tid * 16];
            #pragma unroll
            for (int q = 1; q < 16; q++) {
                float v = redv[tid * 16 + q];
                int ii = redi[tid * 16 + q];
                if (v < bv || (v == bv && ii < bi)) { bv = v; bi = ii; }
            }
            g_bestval[ns * BHW + row0 + tid] = bv;
            g_bestidx[ns * BHW + row0 + tid] = bi;
        }
        __syncthreads();   // scratch free before next tile's prologue
    }
}

// ---------------- 5) reduce the NSPL candidates per row (ties -> lowest idx) -
// splits are n-ascending, so strict < keeps the lowest index globally.
__global__ void k_finalize(void) {
    int r = blockIdx.x * blockDim.x + threadIdx.x;
    if (r >= BHW) return;
    float bv = g_bestval[r];
    int bi = g_bestidx[r];
    for (int s = 1; s < NSPL; s++) {
        float v = g_bestval[s * BHW + r];
        int ii = g_bestidx[s * BHW + r];
        if (v < bv || (v == bv && ii < bi)) { bv = v; bi = ii; }
    }
    g_idx[r] = bi;
}

// ---------------- 6) straight-through output + per-block loss partials -------
// Reference: z_q_out = fl(zb + fl(z_q - zb))  (two roundings — NOT just z_q!)
__global__ void k_output(const float* __restrict__ z, const float* __restrict__ E,
                         float* __restrict__ out) {
    int p = blockIdx.x * 1024 + threadIdx.x;   // index into z layout (B,C,H,W)
    int b = p >> 18;
    int c = (p >> 10) & 255;
    int hw = p & 1023;
    int row = (b << 10) + hw;
    float zv = z[p];
    float e = E[(size_t)g_idx[row] * CDIM + c];
    float d = __fadd_rn(e, -zv);               // fl(z_q - zb)
    out[p] = __fadd_rn(zv, d);                 // fl(zb + fl(z_q - zb))
    __shared__ float sm[1024];
    sm[threadIdx.x] = d * d;
    __syncthreads();
    #pragma unroll
    for (int o = 512; o; o >>= 1) {
        if (threadIdx.x < o) sm[threadIdx.x] += sm[threadIdx.x + o];
        __syncthreads();
    }
    if (threadIdx.x == 0) g_losspart[blockIdx.x] = sm[0];
}

// ---------------- 7) final loss reduce (deterministic) -----------------------
__global__ void k_loss(float* __restrict__ out, int out_size) {
    __shared__ float sm[1024];
    sm[threadIdx.x] = g_losspart[threadIdx.x] + g_losspart[threadIdx.x + 1024];
    __syncthreads();
    #pragma unroll
    for (int o = 512; o; o >>= 1) {
        if (threadIdx.x < o) sm[threadIdx.x] += sm[threadIdx.x + o];
        __syncthreads();
    }
    if (threadIdx.x == 0 && out_size > BHW * CDIM) {
        // loss = beta*mean + mean = 2*mean over 2,097,152 elements
        out[BHW * CDIM] = 2.0f * sm[0] / (float)(BHW * CDIM);
    }
}

extern "C" void kernel_launch(void* const* d_in, const int* in_sizes, int n_in,
                              void* d_out, int out_size) {
    const float* z = (const float*)d_in[0];        // (8,256,32,32)
    const float* E = (const float*)d_in[1];        // (16384,256)
    float* out = (float*)d_out;

    const int smem_bytes = 2 * STAGE_FLOATS * 4;   // 101376 B, double-buffered
    cudaFuncSetAttribute(k_gemm_argmin,
                         cudaFuncAttributeMaxDynamicSharedMemorySize, smem_bytes);

    k_zcopy<<<8192, 256>>>(z);
    k_etrans<<<dim3(512, 8), dim3(32, 32)>>>(E);
    k_rownorm<<<32, 256>>>();
    k_gemm_argmin<<<GRIDX, 256, smem_bytes>>>();
    k_finalize<<<32, 256>>>();
    k_output<<<2048, 1024>>>(z, E, out);
    k_loss<<<1, 1024>>>(out, out_size);
}